// round 1
// baseline (speedup 1.0000x reference)
#include <cuda_runtime.h>

// Problem constants
#define B_    32
#define FIN   64
#define FOUT  64
#define DD    512
#define KK    64
#define KTOT  (KK * DD)      // 32768 (flattened reduction dim of stage-2 GEMM)
#define MM    (B_ * FOUT)    // 2048  (rows of stage-2 GEMM)
#define SPLIT 8
#define KS    (KTOT / SPLIT) // 4096 per split-K chunk

// Scratch: __device__ globals (no allocation anywhere, per harness rules)
__device__ float g_T[(size_t)MM * KTOT];            // 256 MB: T[(b*64+o)][(k*512+e)]
__device__ float g_part[(size_t)SPLIT * MM * DD];   // 32 MB : split-K partials

// ---------------------------------------------------------------------------
// Stage 1: T[b*64+o][k*512+e] = sum_i coeff[o,i,k] * x[b,i,e]
// grid (4 e-chunks of 128, K=64, B=32), 256 threads
// ---------------------------------------------------------------------------
__global__ void __launch_bounds__(256) stage1_kernel(const float* __restrict__ x,
                                                     const float* __restrict__ coeff) {
    const int e0 = blockIdx.x * 128;
    const int k  = blockIdx.y;
    const int b  = blockIdx.z;

    __shared__ __align__(16) float sC[64][68];   // [i][o], padded (row%4==0 for float4, banks split)
    __shared__ __align__(16) float sX[64][128];  // [i][e]

    const int tid = threadIdx.x;

    // Load coeff[:, :, k] transposed -> sC[i][o]   (strided gather; L2-resident, reused over b,e)
    for (int idx = tid; idx < 64 * 64; idx += 256) {
        int o = idx >> 6, i = idx & 63;
        sC[i][o] = coeff[(o * 64 + i) * 64 + k];
    }
    // Load x[b, :, e0:e0+128] -> sX  (coalesced float4)
    for (int idx = tid; idx < 64 * 32; idx += 256) {
        int i = idx >> 5, eq = (idx & 31) << 2;
        *(float4*)&sX[i][eq] = *(const float4*)&x[(b * 64 + i) * 512 + e0 + eq];
    }
    __syncthreads();

    const int tx = tid & 31;   // e-group: 4 e's
    const int ty = tid >> 5;   // o-group: 8 o's

    float acc[8][4];
#pragma unroll
    for (int o = 0; o < 8; ++o)
#pragma unroll
        for (int e = 0; e < 4; ++e) acc[o][e] = 0.0f;

#pragma unroll 8
    for (int i = 0; i < 64; ++i) {
        float4 xv = *(float4*)&sX[i][tx * 4];
        float c[8];
        *(float4*)&c[0] = *(float4*)&sC[i][ty * 8];
        *(float4*)&c[4] = *(float4*)&sC[i][ty * 8 + 4];
#pragma unroll
        for (int o = 0; o < 8; ++o) {
            acc[o][0] += c[o] * xv.x;
            acc[o][1] += c[o] * xv.y;
            acc[o][2] += c[o] * xv.z;
            acc[o][3] += c[o] * xv.w;
        }
    }

    // Store to T: row = b*64 + o, col = k*512 + e0 + e   (coalesced float4 per o-row)
#pragma unroll
    for (int o = 0; o < 8; ++o) {
        size_t row = (size_t)(b * 64 + ty * 8 + o);
        float* dst = g_T + row * KTOT + (size_t)k * 512 + e0 + tx * 4;
        *(float4*)dst = make_float4(acc[o][0], acc[o][1], acc[o][2], acc[o][3]);
    }
}

// ---------------------------------------------------------------------------
// Stage 2: split-K SGEMM  C_part[s] = T[:, s-chunk] @ Wflat[s-chunk, :]
// A = g_T [2048 x 32768] row-major, B = word_ops viewed [32768 x 512] row-major
// BM=128, BN=128, BK=8, 256 threads, 8x8 micro-tiles, double-buffered smem
// grid (N/128=4, M/128=16, SPLIT=8) = 512 blocks
// ---------------------------------------------------------------------------
__global__ void __launch_bounds__(256) sgemm_splitk_kernel(const float* __restrict__ Bmat) {
    const int n0 = blockIdx.x * 128;
    const int m0 = blockIdx.y * 128;
    const int k0 = blockIdx.z * KS;

    __shared__ __align__(16) float sA[2][8][132];  // [k][m], padded: conflict-free scalar stores
    __shared__ __align__(16) float sB[2][8][128];  // [k][n]

    const int tid  = threadIdx.x;
    const int arow = tid >> 1;              // 0..127
    const int akq  = (tid & 1) << 2;        // 0 or 4
    const int bkr  = tid >> 5;              // 0..7
    const int bnq  = (tid & 31) << 2;       // 0..124

    const float* Ap = g_T + (size_t)(m0 + arow) * KTOT + k0 + akq;
    const float* Bp = Bmat + (size_t)(k0 + bkr) * DD + n0 + bnq;

    const int tx = tid & 15;  // n micro-tile: tx*8
    const int ty = tid >> 4;  // m micro-tile: ty*8

    float acc[8][8];
#pragma unroll
    for (int i = 0; i < 8; ++i)
#pragma unroll
        for (int j = 0; j < 8; ++j) acc[i][j] = 0.0f;

    // Prologue: tile 0
    {
        float4 av = *(const float4*)Ap;
        float4 bv = *(const float4*)Bp;
        sA[0][akq + 0][arow] = av.x;
        sA[0][akq + 1][arow] = av.y;
        sA[0][akq + 2][arow] = av.z;
        sA[0][akq + 3][arow] = av.w;
        *(float4*)&sB[0][bkr][bnq] = bv;
    }
    __syncthreads();

    int buf = 0;
    const int NT = KS / 8;  // 512 k-tiles
    for (int kt = 0; kt < NT; ++kt) {
        float4 av2, bv2;
        const bool has_next = (kt + 1 < NT);
        if (has_next) {
            av2 = *(const float4*)(Ap + (kt + 1) * 8);
            bv2 = *(const float4*)(Bp + (size_t)(kt + 1) * 8 * DD);
        }

#pragma unroll
        for (int kk = 0; kk < 8; ++kk) {
            float a[8], bb[8];
            *(float4*)&a[0]  = *(float4*)&sA[buf][kk][ty * 8];
            *(float4*)&a[4]  = *(float4*)&sA[buf][kk][ty * 8 + 4];
            *(float4*)&bb[0] = *(float4*)&sB[buf][kk][tx * 8];
            *(float4*)&bb[4] = *(float4*)&sB[buf][kk][tx * 8 + 4];
#pragma unroll
            for (int i = 0; i < 8; ++i)
#pragma unroll
                for (int j = 0; j < 8; ++j) acc[i][j] += a[i] * bb[j];
        }

        if (has_next) {
            buf ^= 1;
            sA[buf][akq + 0][arow] = av2.x;
            sA[buf][akq + 1][arow] = av2.y;
            sA[buf][akq + 2][arow] = av2.z;
            sA[buf][akq + 3][arow] = av2.w;
            *(float4*)&sB[buf][bkr][bnq] = bv2;
        }
        __syncthreads();
    }

    float* Cp = g_part + (size_t)blockIdx.z * MM * DD;
#pragma unroll
    for (int i = 0; i < 8; ++i) {
        float* row = Cp + (size_t)(m0 + ty * 8 + i) * DD + n0 + tx * 8;
        *(float4*)row       = make_float4(acc[i][0], acc[i][1], acc[i][2], acc[i][3]);
        *(float4*)(row + 4) = make_float4(acc[i][4], acc[i][5], acc[i][6], acc[i][7]);
    }
}

// ---------------------------------------------------------------------------
// Reduce split-K partials into d_out (deterministic; writes every element)
// ---------------------------------------------------------------------------
__global__ void __launch_bounds__(256) reduce_kernel(float* __restrict__ out) {
    const int idx = blockIdx.x * 256 + threadIdx.x;  // float4 index, total 262144
    const float4* p = (const float4*)g_part;
    float4 s = p[idx];
#pragma unroll
    for (int sp = 1; sp < SPLIT; ++sp) {
        float4 v = p[(size_t)sp * (MM * DD / 4) + idx];
        s.x += v.x; s.y += v.y; s.z += v.z; s.w += v.w;
    }
    ((float4*)out)[idx] = s;
}

extern "C" void kernel_launch(void* const* d_in, const int* in_sizes, int n_in,
                              void* d_out, int out_size) {
    const float* x     = (const float*)d_in[0];  // [32,64,512]
    const float* w     = (const float*)d_in[1];  // [64,512,512]
    const float* coeff = (const float*)d_in[2];  // [64,64,64]
    float* out = (float*)d_out;                  // [32,64,512]

    stage1_kernel<<<dim3(4, KK, B_), 256>>>(x, coeff);
    sgemm_splitk_kernel<<<dim3(DD / 128, MM / 128, SPLIT), 256>>>(w);
    reduce_kernel<<<(MM * DD / 4) / 256, 256>>>(out);
}